// round 14
// baseline (speedup 1.0000x reference)
#include <cuda_runtime.h>
#include <cuda_bf16.h>

// DTW 2048x2048 anti-diagonal wavefront, single CTA, 8 warps, 8 rows/thread.
// R11 engine (warp-skew pipeline, cta-scope acquire/release counters,
// 16-diag batches, VIMNMX3 3-input min, register-prefetched y and ring,
// float4-batched ring stores) plus latency restructuring:
//  * Cross-step shfl pipelining: each step computes rows 1..7, issues the
//    shfl of nv[7] for the NEXT step, then finishes row 0 with the PREVIOUS
//    step's shfl result (upCur). The 26-cyc shfl latency is fully hidden.
//    Lane 0 is re-patched from up_first after each batch's poll (the only
//    in-batch bu[] reads needing a guarantee are u<=14, covered by need1).
//  * Sticky poll: last-seen progress counters are cached; re-poll only when
//    insufficient -> ~half the acquire-polls skipped in steady state.
//  * SRING=128 (more slack) and y-prefetch issued BEFORE the poll.
// Out-of-range cells stay +inf (left) or finite garbage that flows only
// rightward (right) -- never into valid cells; no predicates.

#define NLEN  2048
#define NW    8
#define RPT   8
#define KB    16
#define NB    255           // full batches (255*16 = 4080)
#define TAIL  15            // 4080 + 15 = 4095 diagonals
#define SRING 128
#define FINF  __int_as_float(0x7f800000)

__device__ __forceinline__ unsigned smem_u32(const void* p) {
    return (unsigned)__cvta_generic_to_shared(p);
}
__device__ __forceinline__ int ld_acq(const int* p) {
    int v; unsigned a = smem_u32(p);
    asm volatile("ld.acquire.cta.shared::cta.b32 %0, [%1];" : "=r"(v) : "r"(a) : "memory");
    return v;
}
__device__ __forceinline__ void st_rel(int* p, int v) {
    unsigned a = smem_u32(p);
    asm volatile("st.release.cta.shared::cta.b32 [%0], %1;" :: "r"(a), "r"(v) : "memory");
}
__device__ __forceinline__ void lds128(float& a, float& b, float& c, float& d, unsigned addr) {
    asm volatile("ld.shared.v4.f32 {%0,%1,%2,%3}, [%4];"
                 : "=f"(a), "=f"(b), "=f"(c), "=f"(d) : "r"(addr));
}
// min of three nonnegative floats (incl. +inf): IEEE order == signed-int order.
__device__ __forceinline__ float fmin3_nn(float a, float b, float c) {
    int r = __vimin3_s32(__float_as_int(a), __float_as_int(b), __float_as_int(c));
    return __int_as_float(r);
}

__global__ __launch_bounds__(NW * 32, 1)
void dtw_pipe_kernel(const float* __restrict__ x,
                     const float* __restrict__ y,
                     float* __restrict__ out)
{
    __shared__ float ysp[3 * NLEN];                      // ysp[NLEN+j] = y[j], pads 0
    __shared__ __align__(16) float ring[NW + 1][SRING];
    __shared__ int prog[NW + 2];

    const int t    = threadIdx.x;
    const int lane = t & 31;
    const int w    = t >> 5;

    for (int k = t; k < 3 * NLEN; k += NW * 32) {
        int j = k - NLEN;
        ysp[k] = ((unsigned)j < (unsigned)NLEN) ? y[j] : 0.0f;
    }
    for (int k = t; k < (NW + 1) * SRING; k += NW * 32)
        (&ring[0][0])[k] = FINF;           // ring[0] = phantom producer (+inf)
    if (t < NW + 2)
        prog[t] = (t == 0 || t == NW + 1) ? 0x7fffffff : -1;

    const int i0 = w * 256 + lane * RPT;   // this thread's top row

    float xv[RPT];
    {
        float4 a = reinterpret_cast<const float4*>(x + i0)[0];
        float4 b = reinterpret_cast<const float4*>(x + i0)[1];
        xv[0]=a.x; xv[1]=a.y; xv[2]=a.z; xv[3]=a.w;
        xv[4]=b.x; xv[5]=b.y; xv[6]=b.z; xv[7]=b.w;
    }

    float p[RPT], pp[RPT];
    #pragma unroll
    for (int r = 0; r < RPT; ++r) { p[r] = FINF; pp[r] = FINF; }
    float dTop  = (t == 0) ? 0.0f : FINF;  // virtual DTW[-1][-1]=0 seeds (0,0)
    float upCur = FINF;                    // 'up' for the upcoming step (d=0)

    __syncthreads();

    const unsigned ybase = smem_u32(ysp) + (unsigned)((NLEN - i0 - 8) << 2);
    const unsigned rpadd = smem_u32(&ring[w][0]);
    float* ringself = ring[w + 1];

    // Step: rows 1..7 (independent), shfl nv[7] for NEXT step, row 0 with the
    // PREVIOUS step's shfl (upCur). Lane0 takes bu[u] (valid for u<=14; the
    // u==15 value is dead -- overwritten by up_first at the next batch head).
    #define STEP_CORE(u)                                                        \
        float nv[RPT];                                                          \
        _Pragma("unroll")                                                       \
        for (int r = 1; r < RPT; ++r) {                                         \
            const float dy = xv[r] - yv[8 + (u) - r];                           \
            nv[r] = fmaf(dy, dy, fmin3_nn(p[r-1], pp[r-1], p[r]));              \
        }                                                                       \
        float upNext = __shfl_up_sync(0xffffffffu, nv[RPT - 1], 1);             \
        {                                                                       \
            const float dy = xv[0] - yv[8 + (u)];                               \
            nv[0] = fmaf(dy, dy, fmin3_nn(upCur, dTop, p[0]));                  \
        }                                                                       \
        if (lane == 0) upNext = bu[(u)];                                        \
        dTop = upCur; upCur = upNext;                                           \
        _Pragma("unroll")                                                       \
        for (int r = 0; r < RPT; ++r) { pp[r] = p[r]; p[r] = nv[r]; }

    int hv1 = -1, hv2 = -1;                // sticky last-seen progress values

    for (int m = 0; m <= NB; ++m) {
        const int d0 = m * KB;
        const bool full = (m < NB);
        const int steps = full ? KB : TAIL;
        const int need1 = d0 + steps - 2;               // upstream wrote through here
        const int need2 = d0 + steps - 1 - (SRING - 1); // downstream within slack

        // y prefetch first: independent of the poll, overlaps its latency.
        float yv[24];
        {
            const unsigned b = ybase + (unsigned)(d0 << 2);
            #pragma unroll
            for (int v = 0; v < 6; ++v)
                lds128(yv[4*v], yv[4*v+1], yv[4*v+2], yv[4*v+3], b + 16u * v);
        }

        if (hv1 < need1 || hv2 < need2) {
            do { hv1 = ld_acq(prog + w); hv2 = ld_acq(prog + w + 2); }
            while (hv1 < need1 || hv2 < need2);
        }

        // Ring prefetch (post-guarantee): bu[k] = prev warp at diagonal d0+k.
        float bu[16];
        {
            const unsigned s = (unsigned)(d0 & (SRING - 1)) << 2;   // no wrap in batch
            lds128(bu[0],  bu[1],  bu[2],  bu[3],  rpadd + s);
            lds128(bu[4],  bu[5],  bu[6],  bu[7],  rpadd + s + 16);
            lds128(bu[8],  bu[9],  bu[10], bu[11], rpadd + s + 32);
            lds128(bu[12], bu[13], bu[14], bu[15], rpadd + s + 48);
        }
        // Re-patch lane0's pending 'up' (for this batch's step 0): diag d0-1.
        if (lane == 0) upCur = ring[w][(d0 - 1) & (SRING - 1)];

        float* rs = ringself + (d0 & (SRING - 1));

        if (full) {
            float4 b4;
            #pragma unroll
            for (int u = 0; u < KB; ++u) {
                STEP_CORE(u)
                if ((u & 3) == 0) b4.x = nv[RPT-1];
                if ((u & 3) == 1) b4.y = nv[RPT-1];
                if ((u & 3) == 2) b4.z = nv[RPT-1];
                if ((u & 3) == 3) {
                    b4.w = nv[RPT-1];
                    if (lane == 31) *reinterpret_cast<float4*>(rs + (u - 3)) = b4;
                }
            }
        } else {
            #pragma unroll
            for (int u = 0; u < TAIL; ++u) {
                STEP_CORE(u)
                if (lane == 31) rs[u] = nv[RPT-1];   // tail runs once: scalar stores
            }
        }

        if (lane == 31) st_rel(prog + w + 1, d0 + steps - 1);
    }
    #undef STEP_CORE

    // Warp 7, lane 31, bottom row 2047: value at d = 4094 is p[7] after rotation.
    if (t == NW * 32 - 1) out[0] = sqrtf(p[RPT - 1]);
}

extern "C" void kernel_launch(void* const* d_in, const int* in_sizes, int n_in,
                              void* d_out, int out_size)
{
    const float* x = (const float*)d_in[0];
    const float* y = (const float*)d_in[1];
    float* out = (float*)d_out;
    dtw_pipe_kernel<<<1, NW * 32>>>(x, y, out);
}

// round 16
// speedup vs baseline: 1.2080x; 1.2080x over previous
#include <cuda_runtime.h>
#include <cuda_bf16.h>

// DTW 2048x2048 anti-diagonal wavefront, single CTA, 8 warps, 8 rows/thread.
// R11 engine (warp-skew pipeline, cta-scope acquire/release counters,
// VIMNMX3 3-input min, register-prefetched y/ring, float4 ring stores,
// sticky polls) with two crossbar/overhead fixes:
//  * y stored in a padded layout phys(j) = j + (j>>3)*4: thread lane stride
//    becomes 48B, which makes every 8-lane phase of an LDS.128 hit 8 distinct
//    16B bank groups -> conflict-free (old layout: 32B stride, 2-way/phase).
//    8-float groups stay contiguous & 16B-aligned, loaded as 2x LDS.128 at
//    compile-time offsets (window bases are multiples of 8).
//  * KB=32 diagonals per batch: poll/setup/store-release overhead per
//    diagonal halved. Ring slots d0..d0+31 cannot be recycled by the
//    upstream warp until our progress publishes (SRING=128), so the batch
//    prefetch of bu[] stays race-free.
// Out-of-range cells stay +inf (left edge) or finite garbage that only
// flows rightward (right edge) -- never into valid cells; no predicates.

#define NLEN  2048
#define NW    8
#define RPT   8
#define KB    32
#define NB    127           // full batches (127*32 = 4064)
#define TAIL  31            // 4064 + 31 = 4095 diagonals
#define SRING 128
#define FINF  __int_as_float(0x7f800000)

// padded y layout: phys(j) = j + (j>>3)*4  (4-float pad after every 8)
#define YPHYS(j) ((j) + (((j) >> 3) << 2))
#define YPADN (YPHYS(3 * NLEN) + 8)        // 9224 floats ≈ 36.9 KB

__device__ __forceinline__ unsigned smem_u32(const void* p) {
    return (unsigned)__cvta_generic_to_shared(p);
}
__device__ __forceinline__ int ld_acq(const int* p) {
    int v; unsigned a = smem_u32(p);
    asm volatile("ld.acquire.cta.shared::cta.b32 %0, [%1];" : "=r"(v) : "r"(a) : "memory");
    return v;
}
__device__ __forceinline__ void st_rel(int* p, int v) {
    unsigned a = smem_u32(p);
    asm volatile("st.release.cta.shared::cta.b32 [%0], %1;" :: "r"(a), "r"(v) : "memory");
}
__device__ __forceinline__ void lds128(float& a, float& b, float& c, float& d, unsigned addr) {
    asm volatile("ld.shared.v4.f32 {%0,%1,%2,%3}, [%4];"
                 : "=f"(a), "=f"(b), "=f"(c), "=f"(d) : "r"(addr));
}
// min of three nonnegative floats (incl. +inf): IEEE order == signed-int order.
__device__ __forceinline__ float fmin3_nn(float a, float b, float c) {
    int r = __vimin3_s32(__float_as_int(a), __float_as_int(b), __float_as_int(c));
    return __int_as_float(r);
}

__global__ __launch_bounds__(NW * 32, 1)
void dtw_kb32_kernel(const float* __restrict__ x,
                     const float* __restrict__ y,
                     float* __restrict__ out)
{
    __shared__ float ypad[YPADN];                        // ypad[phys(NLEN+j)] = y[j], pads 0
    __shared__ __align__(16) float ring[NW + 1][SRING];  // ring[w+1][d&127] = warp w bottom row at d
    __shared__ int prog[NW + 2];

    const int t    = threadIdx.x;
    const int lane = t & 31;
    const int w    = t >> 5;

    for (int k = t; k < 3 * NLEN; k += NW * 32) {
        int j = k - NLEN;
        ypad[YPHYS(k)] = ((unsigned)j < (unsigned)NLEN) ? y[j] : 0.0f;
    }
    for (int k = t; k < (NW + 1) * SRING; k += NW * 32)
        (&ring[0][0])[k] = FINF;           // ring[0] = phantom producer (+inf)
    if (t < NW + 2)
        prog[t] = (t == 0 || t == NW + 1) ? 0x7fffffff : -1;

    const int i0 = w * 256 + lane * RPT;   // this thread's top row

    float xv[RPT];
    {
        float4 a = reinterpret_cast<const float4*>(x + i0)[0];
        float4 b = reinterpret_cast<const float4*>(x + i0)[1];
        xv[0]=a.x; xv[1]=a.y; xv[2]=a.z; xv[3]=a.w;
        xv[4]=b.x; xv[5]=b.y; xv[6]=b.z; xv[7]=b.w;
    }

    float p[RPT], pp[RPT];
    #pragma unroll
    for (int r = 0; r < RPT; ++r) { p[r] = FINF; pp[r] = FINF; }
    float dTop = (t == 0) ? 0.0f : FINF;   // virtual DTW[-1][-1]=0 seeds (0,0)

    __syncthreads();

    // Window base for batch at d0: logical index yoff - 8 + d0 (multiple of 8).
    // phys is additive over multiples of 8; phys(d0) bytes = 6*d0.
    const int yoff = NLEN - i0;
    const unsigned ybase = smem_u32(ypad) + (unsigned)(YPHYS(yoff - 8) << 2);
    const unsigned rpadd = smem_u32(&ring[w][0]);
    float* ringself = ring[w + 1];

    #define STEP_CORE(u)                                                        \
        float up = __shfl_up_sync(0xffffffffu, p[RPT - 1], 1);                  \
        if (lane == 0) up = ((u) == 0) ? up_first : bu[(u) - 1];                \
        float nv[RPT];                                                          \
        {                                                                       \
            const float dy = xv[0] - yv[8 + (u)];                               \
            nv[0] = fmaf(dy, dy, fmin3_nn(up, dTop, p[0]));                     \
        }                                                                       \
        _Pragma("unroll")                                                       \
        for (int r = 1; r < RPT; ++r) {                                         \
            const float dy = xv[r] - yv[8 + (u) - r];                           \
            nv[r] = fmaf(dy, dy, fmin3_nn(p[r-1], pp[r-1], p[r]));              \
        }                                                                       \
        dTop = up;                                                              \
        _Pragma("unroll")                                                       \
        for (int r = 0; r < RPT; ++r) { pp[r] = p[r]; p[r] = nv[r]; }

    int hv1 = -1, hv2 = -1;                // sticky last-seen progress values

    for (int m = 0; m <= NB; ++m) {
        const int d0 = m * KB;
        const bool full = (m < NB);
        const int steps = full ? KB : TAIL;
        const int need1 = d0 + steps - 2;               // upstream wrote through here
        const int need2 = d0 + steps - 1 - (SRING - 1); // downstream within ring slack

        // y prefetch first (independent of the poll, overlaps its latency).
        // 40-float window = 5 groups of 8 contiguous floats, 48B group stride.
        float yv[40];
        {
            const unsigned b = ybase + (unsigned)(6 * d0);   // phys(d0) bytes
            #pragma unroll
            for (int g = 0; g < 5; ++g) {
                lds128(yv[8*g+0], yv[8*g+1], yv[8*g+2], yv[8*g+3], b + 48u*g);
                lds128(yv[8*g+4], yv[8*g+5], yv[8*g+6], yv[8*g+7], b + 48u*g + 16u);
            }
        }

        if (hv1 < need1 || hv2 < need2) {
            do { hv1 = ld_acq(prog + w); hv2 = ld_acq(prog + w + 2); }
            while (hv1 < need1 || hv2 < need2);
        }

        // Ring prefetch (post-guarantee): bu[k] = prev warp at diagonal d0+k.
        // Slots d0.. can't be recycled until our own prog publishes.
        float bu[KB];
        {
            const unsigned s = (unsigned)(d0 & (SRING - 1)) << 2;  // no wrap in batch
            #pragma unroll
            for (int v = 0; v < KB / 4; ++v)
                lds128(bu[4*v], bu[4*v+1], bu[4*v+2], bu[4*v+3], rpadd + s + 16u*v);
        }
        const float up_first = ring[w][(d0 - 1) & (SRING - 1)];

        float* rs = ringself + (d0 & (SRING - 1));

        if (full) {
            float4 b4;
            #pragma unroll
            for (int u = 0; u < KB; ++u) {
                STEP_CORE(u)
                if ((u & 3) == 0) b4.x = nv[RPT-1];
                if ((u & 3) == 1) b4.y = nv[RPT-1];
                if ((u & 3) == 2) b4.z = nv[RPT-1];
                if ((u & 3) == 3) {
                    b4.w = nv[RPT-1];
                    if (lane == 31) *reinterpret_cast<float4*>(rs + (u - 3)) = b4;
                }
            }
        } else {
            #pragma unroll
            for (int u = 0; u < TAIL; ++u) {
                STEP_CORE(u)
                if (lane == 31) rs[u] = nv[RPT-1];   // tail runs once: scalar stores
            }
        }

        if (lane == 31) st_rel(prog + w + 1, d0 + steps - 1);
    }
    #undef STEP_CORE

    // Warp 7, lane 31, bottom row 2047: value at d = 4094 is p[7] after rotation.
    if (t == NW * 32 - 1) out[0] = sqrtf(p[RPT - 1]);
}

extern "C" void kernel_launch(void* const* d_in, const int* in_sizes, int n_in,
                              void* d_out, int out_size)
{
    const float* x = (const float*)d_in[0];
    const float* y = (const float*)d_in[1];
    float* out = (float*)d_out;
    dtw_kb32_kernel<<<1, NW * 32>>>(x, y, out);
}

// round 17
// speedup vs baseline: 1.5355x; 1.2712x over previous
#include <cuda_runtime.h>
#include <cuda_bf16.h>

// DTW 2048x2048 anti-diagonal wavefront, single CTA, 8 warps, 8 rows/thread.
// R16 engine (warp-skew pipeline, cta-scope acquire/release counters, KB=32
// batches, VIMNMX3 3-input min, conflict-free padded-y register prefetch,
// ring register prefetch, float4 ring stores, sticky polls) plus
// ACTIVE-WINDOW TRIMMING: warp w's 256-row band only intersects diagonals
// [256w, 256w+2302], so it runs exactly 72 batches starting at batch 8w
// (2304 diagonals) instead of all 4095 -- the other 44% of steps only ever
// computed provably-garbage cells (j<0 or j>2047).
//  * prog[k] (warp k-1's counter) inits to 256(k-1)-1: claims everything
//    below its start consumed/produced; consumer k's smallest read is
//    256k-1, above the claim -> safe.
//  * After its last batch each warp publishes prog=INF: downstream polls
//    for diagonals beyond the producer's window feed only out-of-range
//    columns (garbage cells), so unconditional success is correct.
//  * Fill-phase: warp w hits backpressure at d0=256w+352 but satisfies
//    downstream's first need at d0=256w+288 -> no deadlock.
// Out-of-range cells stay +inf (left edge) or finite garbage that only
// flows rightward (right edge) -- never into valid cells.

#define NLEN  2048
#define NW    8
#define RPT   8
#define KB    32
#define NB    127           // last global batch index (tail)
#define TAIL  31
#define NBW   72            // batches per warp (72*32 = 2304 >= 2303 active)
#define SRING 128
#define FINF  __int_as_float(0x7f800000)
#define PINF  0x7fffffff

// padded y layout: phys(j) = j + (j>>3)*4  (4-float pad after every 8)
#define YPHYS(j) ((j) + (((j) >> 3) << 2))
#define YPADN (YPHYS(3 * NLEN) + 8)

__device__ __forceinline__ unsigned smem_u32(const void* p) {
    return (unsigned)__cvta_generic_to_shared(p);
}
__device__ __forceinline__ int ld_acq(const int* p) {
    int v; unsigned a = smem_u32(p);
    asm volatile("ld.acquire.cta.shared::cta.b32 %0, [%1];" : "=r"(v) : "r"(a) : "memory");
    return v;
}
__device__ __forceinline__ void st_rel(int* p, int v) {
    unsigned a = smem_u32(p);
    asm volatile("st.release.cta.shared::cta.b32 [%0], %1;" :: "r"(a), "r"(v) : "memory");
}
__device__ __forceinline__ void lds128(float& a, float& b, float& c, float& d, unsigned addr) {
    asm volatile("ld.shared.v4.f32 {%0,%1,%2,%3}, [%4];"
                 : "=f"(a), "=f"(b), "=f"(c), "=f"(d) : "r"(addr));
}
// min of three nonnegative floats (incl. +inf): IEEE order == signed-int order.
__device__ __forceinline__ float fmin3_nn(float a, float b, float c) {
    int r = __vimin3_s32(__float_as_int(a), __float_as_int(b), __float_as_int(c));
    return __int_as_float(r);
}

__global__ __launch_bounds__(NW * 32, 1)
void dtw_trim_kernel(const float* __restrict__ x,
                     const float* __restrict__ y,
                     float* __restrict__ out)
{
    __shared__ float ypad[YPADN];                        // ypad[phys(NLEN+j)] = y[j], pads 0
    __shared__ __align__(16) float ring[NW + 1][SRING];  // ring[w+1][d&127] = warp w bottom row at d
    __shared__ int prog[NW + 2];

    const int t    = threadIdx.x;
    const int lane = t & 31;
    const int w    = t >> 5;

    for (int k = t; k < 3 * NLEN; k += NW * 32) {
        int j = k - NLEN;
        ypad[YPHYS(k)] = ((unsigned)j < (unsigned)NLEN) ? y[j] : 0.0f;
    }
    for (int k = t; k < (NW + 1) * SRING; k += NW * 32)
        (&ring[0][0])[k] = FINF;           // ring[0] = phantom producer (+inf)
    if (t < NW + 2) {
        int v;
        if (t == 0 || t == NW + 1) v = PINF;          // phantom upstream / downstream
        else                       v = 256 * (t - 1) - 1;  // warp t-1 starts at diag 256(t-1)
        prog[t] = v;
    }

    const int i0 = w * 256 + lane * RPT;   // this thread's top row

    float xv[RPT];
    {
        float4 a = reinterpret_cast<const float4*>(x + i0)[0];
        float4 b = reinterpret_cast<const float4*>(x + i0)[1];
        xv[0]=a.x; xv[1]=a.y; xv[2]=a.z; xv[3]=a.w;
        xv[4]=b.x; xv[5]=b.y; xv[6]=b.z; xv[7]=b.w;
    }

    float p[RPT], pp[RPT];
    #pragma unroll
    for (int r = 0; r < RPT; ++r) { p[r] = FINF; pp[r] = FINF; }
    float dTop = (t == 0) ? 0.0f : FINF;   // virtual DTW[-1][-1]=0 seeds (0,0)

    __syncthreads();

    const int yoff = NLEN - i0;
    const unsigned ybase = smem_u32(ypad) + (unsigned)(YPHYS(yoff - 8) << 2);
    const unsigned rpadd = smem_u32(&ring[w][0]);
    float* ringself = ring[w + 1];

    #define STEP_CORE(u)                                                        \
        float up = __shfl_up_sync(0xffffffffu, p[RPT - 1], 1);                  \
        if (lane == 0) up = ((u) == 0) ? up_first : bu[(u) - 1];                \
        float nv[RPT];                                                          \
        {                                                                       \
            const float dy = xv[0] - yv[8 + (u)];                               \
            nv[0] = fmaf(dy, dy, fmin3_nn(up, dTop, p[0]));                     \
        }                                                                       \
        _Pragma("unroll")                                                       \
        for (int r = 1; r < RPT; ++r) {                                         \
            const float dy = xv[r] - yv[8 + (u) - r];                           \
            nv[r] = fmaf(dy, dy, fmin3_nn(p[r-1], pp[r-1], p[r]));              \
        }                                                                       \
        dTop = up;                                                              \
        _Pragma("unroll")                                                       \
        for (int r = 0; r < RPT; ++r) { pp[r] = p[r]; p[r] = nv[r]; }

    int hv1 = -1, hv2 = -1;                // sticky last-seen progress values
    const int mstart = 8 * w;              // first batch index for this warp

    for (int mm = 0; mm < NBW; ++mm) {
        const int m  = mstart + mm;
        const int d0 = m * KB;
        const bool full = (m < NB);        // only warp 7's last batch is the tail
        const int steps = full ? KB : TAIL;
        const int need1 = d0 + steps - 2;               // upstream wrote through here
        const int need2 = d0 + steps - 1 - (SRING - 1); // downstream within ring slack

        // y prefetch first (independent of the poll, overlaps its latency).
        float yv[40];
        {
            const unsigned b = ybase + (unsigned)(6 * d0);   // phys(d0) bytes
            #pragma unroll
            for (int g = 0; g < 5; ++g) {
                lds128(yv[8*g+0], yv[8*g+1], yv[8*g+2], yv[8*g+3], b + 48u*g);
                lds128(yv[8*g+4], yv[8*g+5], yv[8*g+6], yv[8*g+7], b + 48u*g + 16u);
            }
        }

        if (hv1 < need1 || hv2 < need2) {
            do { hv1 = ld_acq(prog + w); hv2 = ld_acq(prog + w + 2); }
            while (hv1 < need1 || hv2 < need2);
        }

        // Ring prefetch (post-guarantee): bu[k] = prev warp at diagonal d0+k.
        float bu[KB];
        {
            const unsigned s = (unsigned)(d0 & (SRING - 1)) << 2;  // no wrap in batch
            #pragma unroll
            for (int v = 0; v < KB / 4; ++v)
                lds128(bu[4*v], bu[4*v+1], bu[4*v+2], bu[4*v+3], rpadd + s + 16u*v);
        }
        const float up_first = ring[w][(d0 - 1) & (SRING - 1)];

        float* rs = ringself + (d0 & (SRING - 1));

        if (full) {
            float4 b4;
            #pragma unroll
            for (int u = 0; u < KB; ++u) {
                STEP_CORE(u)
                if ((u & 3) == 0) b4.x = nv[RPT-1];
                if ((u & 3) == 1) b4.y = nv[RPT-1];
                if ((u & 3) == 2) b4.z = nv[RPT-1];
                if ((u & 3) == 3) {
                    b4.w = nv[RPT-1];
                    if (lane == 31) *reinterpret_cast<float4*>(rs + (u - 3)) = b4;
                }
            }
        } else {
            #pragma unroll
            for (int u = 0; u < TAIL; ++u) {
                STEP_CORE(u)
                if (lane == 31) rs[u] = nv[RPT-1];   // tail runs once: scalar stores
            }
        }

        if (lane == 31) st_rel(prog + w + 1, d0 + steps - 1);
    }
    #undef STEP_CORE

    // Past our window: publish "infinite" progress so downstream polls for
    // diagonals we never produce (feeding only j>2047 garbage cells) succeed.
    if (lane == 31) st_rel(prog + w + 1, PINF);

    // Warp 7, lane 31, bottom row 2047: value at d = 4094 is p[7] after rotation.
    if (t == NW * 32 - 1) out[0] = sqrtf(p[RPT - 1]);
}

extern "C" void kernel_launch(void* const* d_in, const int* in_sizes, int n_in,
                              void* d_out, int out_size)
{
    const float* x = (const float*)d_in[0];
    const float* y = (const float*)d_in[1];
    float* out = (float*)d_out;
    dtw_trim_kernel<<<1, NW * 32>>>(x, y, out);
}